// round 6
// baseline (speedup 1.0000x reference)
#include <cuda_runtime.h>
#include <mma.h>
#include <cstdint>
#include <math.h>

using namespace nvcuda;

// Problem constants
constexpr int Bb = 2, Ss = 2048, Ee = 4096, Hh = 16, Dd = 256, Rr = 64;
constexpr int Mtot = Bb * Ss;                  // 4096
constexpr size_t QK_ELEMS = (size_t)Bb * Hh * Ss * Dd;   // 16777216

// GEMM tiling: CTA 128x256, 8 warps in 2x4, each warp 64x64
constexpr int BM = 128, BN = 256, BK = 32;
constexpr int ASTR = BK + 8;                             // 40 floats/row
constexpr uint32_t STAGE_A_BYTES = BM * ASTR * 4;        // 20480
constexpr uint32_t STAGE_B_BYTES = BN * ASTR * 4;        // 40960
constexpr uint32_t STAGE_BYTES = STAGE_A_BYTES + STAGE_B_BYTES;  // 61440
constexpr int NSTAGE = 3;
constexpr int CSTR = BN + 4;                             // 260
constexpr uint32_t GEMM_SMEM = NSTAGE * STAGE_BYTES;     // 184320 (Cs: 128*260*4=133120 fits)

// Scratch
__device__ float g_xnorm[(size_t)Mtot * Ee];
__device__ float g_wq[(size_t)Ee * Ee];
__device__ float g_wk[(size_t)Ee * Ee];
__device__ float g_qr[QK_ELEMS];
__device__ float g_kr[QK_ELEMS];

__device__ __forceinline__ uint32_t smem_u32(const void* p) {
    uint32_t a;
    asm("{ .reg .u64 t; cvta.to.shared.u64 t, %1; cvt.u32.u64 %0, t; }" : "=r"(a) : "l"(p));
    return a;
}
__device__ __forceinline__ void cp16(uint32_t dst, const void* src) {
    asm volatile("cp.async.cg.shared.global [%0], [%1], 16;" :: "r"(dst), "l"(src));
}
#define CP_COMMIT() asm volatile("cp.async.commit_group;" ::: "memory")
#define CP_WAIT2()  asm volatile("cp.async.wait_group 2;" ::: "memory")

// ---------------------------------------------------------------------------
// LayerNorm (tf32-rounded output)
// ---------------------------------------------------------------------------
__global__ void __launch_bounds__(256) ln_kernel(const float* __restrict__ x,
                                                 const float* __restrict__ w,
                                                 const float* __restrict__ b) {
    int row = blockIdx.x;
    int tid = threadIdx.x;
    const float4* xr = reinterpret_cast<const float4*>(x + (size_t)row * Ee);

    float4 v[4];
    float sum = 0.f, ssq = 0.f;
#pragma unroll
    for (int j = 0; j < 4; j++) {
        v[j] = xr[tid + j * 256];
        sum += v[j].x + v[j].y + v[j].z + v[j].w;
        ssq += v[j].x * v[j].x + v[j].y * v[j].y + v[j].z * v[j].z + v[j].w * v[j].w;
    }
    __shared__ float s_sum[8], s_ssq[8];
#pragma unroll
    for (int o = 16; o; o >>= 1) {
        sum += __shfl_xor_sync(~0u, sum, o);
        ssq += __shfl_xor_sync(~0u, ssq, o);
    }
    if ((tid & 31) == 0) { s_sum[tid >> 5] = sum; s_ssq[tid >> 5] = ssq; }
    __syncthreads();
    if (tid < 32) {
        float ts = (tid < 8) ? s_sum[tid] : 0.f;
        float tq = (tid < 8) ? s_ssq[tid] : 0.f;
#pragma unroll
        for (int o = 4; o; o >>= 1) {
            ts += __shfl_xor_sync(~0u, ts, o);
            tq += __shfl_xor_sync(~0u, tq, o);
        }
        if (tid == 0) { s_sum[0] = ts; s_ssq[0] = tq; }
    }
    __syncthreads();
    float mean = s_sum[0] * (1.0f / Ee);
    float var = s_ssq[0] * (1.0f / Ee) - mean * mean;
    float rstd = rsqrtf(var + 1e-5f);

    const float4* wr = reinterpret_cast<const float4*>(w);
    const float4* br = reinterpret_cast<const float4*>(b);
    float4* outr = reinterpret_cast<float4*>(g_xnorm + (size_t)row * Ee);
#pragma unroll
    for (int j = 0; j < 4; j++) {
        int c = tid + j * 256;
        float4 wv = wr[c], bv = br[c], o;
        o.x = wmma::__float_to_tf32((v[j].x - mean) * rstd * wv.x + bv.x);
        o.y = wmma::__float_to_tf32((v[j].y - mean) * rstd * wv.y + bv.y);
        o.z = wmma::__float_to_tf32((v[j].z - mean) * rstd * wv.z + bv.z);
        o.w = wmma::__float_to_tf32((v[j].w - mean) * rstd * wv.w + bv.w);
        outr[c] = o;
    }
}

// ---------------------------------------------------------------------------
// Weight pre-rounding to tf32
// ---------------------------------------------------------------------------
__global__ void __launch_bounds__(256) wconv_kernel(const float* __restrict__ wq,
                                                    const float* __restrict__ wk) {
    const float* src = blockIdx.y ? wk : wq;
    float* dst = blockIdx.y ? g_wk : g_wq;
    size_t i = ((size_t)blockIdx.x * 256 + threadIdx.x) * 4;
    float4 v = *reinterpret_cast<const float4*>(src + i);
    v.x = wmma::__float_to_tf32(v.x);
    v.y = wmma::__float_to_tf32(v.y);
    v.z = wmma::__float_to_tf32(v.z);
    v.w = wmma::__float_to_tf32(v.w);
    *reinterpret_cast<float4*>(dst + i) = v;
}

// ---------------------------------------------------------------------------
// Pipelined tf32 wmma GEMM (NT), CTA tile 128x256, warp tile 64x64
// ---------------------------------------------------------------------------
using AccFrag = wmma::fragment<wmma::accumulator, 16, 16, 8, float>;

__device__ __forceinline__ void load_chunk(uint32_t sb, const char* Ab, const char* Bbp,
                                           size_t ldab, int kc, int buf, int tid) {
    uint32_t stA = sb + buf * STAGE_BYTES;
    uint32_t stB = stA + STAGE_A_BYTES;
    const char* Ap = Ab + (size_t)kc * (BK * 4);
    const char* Bp = Bbp + (size_t)kc * (BK * 4);
#pragma unroll
    for (int l = 0; l < 4; l++) {               // A: 128 rows x 8 chunks
        int idx = tid + l * 256;
        int r = idx >> 3, cb = (idx & 7) << 4;
        cp16(stA + r * (ASTR * 4) + cb, Ap + (size_t)r * ldab + cb);
    }
#pragma unroll
    for (int l = 0; l < 8; l++) {               // B: 256 rows x 8 chunks
        int idx = tid + l * 256;
        int r = idx >> 3, cb = (idx & 7) << 4;
        cp16(stB + r * (ASTR * 4) + cb, Bp + (size_t)r * ldab + cb);
    }
}

template <int NCHUNK>
__device__ __forceinline__ void gemm_pipe(const char* Ab, const char* Bbp, size_t ldab,
                                          char* smem, AccFrag acc[4][4]) {
    uint32_t sb = smem_u32(smem);
    int tid = threadIdx.x;
    int warp = tid >> 5;
    int wm = warp & 1;        // 2 along M, 64 rows each
    int wn = warp >> 1;       // 4 along N, 64 cols each

    load_chunk(sb, Ab, Bbp, ldab, 0, 0, tid);
    CP_COMMIT();
    if (NCHUNK > 1) load_chunk(sb, Ab, Bbp, ldab, 1, 1, tid);
    CP_COMMIT();

    for (int k = 0; k < NCHUNK; k++) {
        if (k + 2 < NCHUNK) load_chunk(sb, Ab, Bbp, ldab, k + 2, (k + 2) % NSTAGE, tid);
        CP_COMMIT();
        CP_WAIT2();
        __syncthreads();

        float* As = reinterpret_cast<float*>(smem + (k % NSTAGE) * STAGE_BYTES);
        float* Bs = reinterpret_cast<float*>(smem + (k % NSTAGE) * STAGE_BYTES + STAGE_A_BYTES);
#pragma unroll
        for (int kk = 0; kk < BK; kk += 8) {
            wmma::fragment<wmma::matrix_a, 16, 16, 8, wmma::precision::tf32, wmma::row_major> af[4];
            wmma::fragment<wmma::matrix_b, 16, 16, 8, wmma::precision::tf32, wmma::col_major> bf[4];
#pragma unroll
            for (int i = 0; i < 4; i++)
                wmma::load_matrix_sync(af[i], As + (wm * 64 + i * 16) * ASTR + kk, ASTR);
#pragma unroll
            for (int j = 0; j < 4; j++)
                wmma::load_matrix_sync(bf[j], Bs + (wn * 64 + j * 16) * ASTR + kk, ASTR);
#pragma unroll
            for (int i = 0; i < 4; i++)
#pragma unroll
                for (int j = 0; j < 4; j++)
                    wmma::mma_sync(acc[i][j], af[i], bf[j], acc[i][j]);
        }
        __syncthreads();
    }
}

__device__ __forceinline__ void store_acc(float* Cs, AccFrag acc[4][4]) {
    int warp = threadIdx.x >> 5;
    int wm = warp & 1, wn = warp >> 1;
#pragma unroll
    for (int i = 0; i < 4; i++)
#pragma unroll
        for (int j = 0; j < 4; j++)
            wmma::store_matrix_sync(Cs + (wm * 64 + i * 16) * CSTR + wn * 64 + j * 16,
                                    acc[i][j], CSTR, wmma::mem_row_major);
}

// ---------------------------------------------------------------------------
// Projection GEMM + bias + RoPE; writes fp32 q/k and tf32-rounded copies
// ---------------------------------------------------------------------------
__global__ void __launch_bounds__(256, 1) proj_cp_kernel(
    const float* __restrict__ bq, const float* __restrict__ bk,
    const float* __restrict__ embed, const int* __restrict__ posids,
    float* __restrict__ qout, float* __restrict__ kout)
{
    extern __shared__ __align__(128) char smem[];
    int z = blockIdx.z;
    const float* W    = z ? g_wk : g_wq;
    const float* bias = z ? bk : bq;
    float* outp       = z ? kout : qout;
    float* routp      = z ? g_kr : g_qr;
    const int m0 = blockIdx.x * BM;   // x fastest: consecutive CTAs share the weight panel
    const int n0 = blockIdx.y * BN;

    AccFrag acc[4][4];
#pragma unroll
    for (int i = 0; i < 4; i++)
#pragma unroll
        for (int j = 0; j < 4; j++)
            wmma::fill_fragment(acc[i][j], 0.f);

    gemm_pipe<Ee / BK>(reinterpret_cast<const char*>(g_xnorm + (size_t)m0 * Ee),
                       reinterpret_cast<const char*>(W + (size_t)n0 * Ee),
                       (size_t)Ee * 4, smem, acc);

    float* Cs = reinterpret_cast<float*>(smem);
    store_acc(Cs, acc);
    __syncthreads();

    int tid = threadIdx.x;
#pragma unroll 4
    for (int i = 0; i < 64; i++) {
        int it = tid + i * 256;          // 0..16383 over 128x128 pairs
        int r = it >> 7;                 // 0..127
        int pc = it & 127;               // pair col 0..127
        int c = pc << 1;
        int m = m0 + r, f = n0 + c;
        float v0 = Cs[r * CSTR + c] + bias[f];
        float v1 = Cs[r * CSTR + c + 1] + bias[f + 1];
        int d = f & 255;
        if (d < Rr) {
            int pos = posids[m];
            int i2 = d >> 1;
            float sn = embed[pos * Rr + i2];
            float co = embed[pos * Rr + 32 + i2];
            float o0 = v0 * co - v1 * sn;
            float o1 = v1 * co + v0 * sn;
            v0 = o0; v1 = o1;
        }
        int b_ = m >> 11, s_ = m & 2047, h_ = f >> 8;
        size_t off = ((size_t)(b_ * Hh + h_) * Ss + s_) * Dd + d;
        *reinterpret_cast<float2*>(outp + off) = make_float2(v0, v1);
        *reinterpret_cast<float2*>(routp + off) =
            make_float2(wmma::__float_to_tf32(v0), wmma::__float_to_tf32(v1));
    }
}

// ---------------------------------------------------------------------------
// Scores GEMM: scores = Qr.Kr^T / 16, causal tile skip (tile 128x256)
// ---------------------------------------------------------------------------
__global__ void __launch_bounds__(256, 1) scores_cp_kernel(float* __restrict__ attn)
{
    int kt = blockIdx.x, qt = blockIdx.y, bh = blockIdx.z;
    int m0 = qt * BM, n0 = kt * BN;
    if (n0 > m0 + BM - 1) return;     // fully masked tile

    extern __shared__ __align__(128) char smem[];
    const float* Q = g_qr + (size_t)bh * Ss * Dd;
    const float* Kv = g_kr + (size_t)bh * Ss * Dd;

    AccFrag acc[4][4];
#pragma unroll
    for (int i = 0; i < 4; i++)
#pragma unroll
        for (int j = 0; j < 4; j++)
            wmma::fill_fragment(acc[i][j], 0.f);

    gemm_pipe<Dd / BK>(reinterpret_cast<const char*>(Q + (size_t)m0 * Dd),
                       reinterpret_cast<const char*>(Kv + (size_t)n0 * Dd),
                       (size_t)Dd * 4, smem, acc);

    float* Cs = reinterpret_cast<float*>(smem);
    store_acc(Cs, acc);
    __syncthreads();

    float* out_base = attn + (size_t)bh * Ss * Ss;
#pragma unroll 4
    for (int i = 0; i < 32; i++) {
        int it = threadIdx.x + i * 256;   // 0..8191 float4s over 128x256
        int r = it >> 6;                  // 0..127
        int c4 = (it & 63) << 2;          // 0..252 step 4
        float4 v = *reinterpret_cast<const float4*>(Cs + r * CSTR + c4);
        v.x *= 0.0625f; v.y *= 0.0625f; v.z *= 0.0625f; v.w *= 0.0625f;
        *reinterpret_cast<float4*>(out_base + (size_t)(m0 + r) * Ss + n0 + c4) = v;
    }
}

// ---------------------------------------------------------------------------
// In-place masked softmax
// ---------------------------------------------------------------------------
__global__ void __launch_bounds__(256) softmax_kernel(float* __restrict__ attn) {
    int row = blockIdx.x;
    int q = row & 2047;
    int nv = q + 1;
    float* rowp = attn + (size_t)row * Ss;
    int tid = threadIdx.x;

    float vals[8];
    float mx = -INFINITY;
#pragma unroll
    for (int j = 0; j < 8; j++) {
        int k = tid + j * 256;
        float v = (k < nv) ? rowp[k] : -INFINITY;
        vals[j] = v;
        mx = fmaxf(mx, v);
    }
    __shared__ float sh[8];
#pragma unroll
    for (int o = 16; o; o >>= 1) mx = fmaxf(mx, __shfl_xor_sync(~0u, mx, o));
    if ((tid & 31) == 0) sh[tid >> 5] = mx;
    __syncthreads();
    if (tid < 32) {
        float t = (tid < 8) ? sh[tid] : -INFINITY;
#pragma unroll
        for (int o = 4; o; o >>= 1) t = fmaxf(t, __shfl_xor_sync(~0u, t, o));
        if (tid == 0) sh[0] = t;
    }
    __syncthreads();
    float M = sh[0];
    __syncthreads();

    float sum = 0.f;
#pragma unroll
    for (int j = 0; j < 8; j++) {
        int k = tid + j * 256;
        float e = (k < nv) ? expf(vals[j] - M) : 0.f;
        vals[j] = e;
        sum += e;
    }
#pragma unroll
    for (int o = 16; o; o >>= 1) sum += __shfl_xor_sync(~0u, sum, o);
    if ((tid & 31) == 0) sh[tid >> 5] = sum;
    __syncthreads();
    if (tid < 32) {
        float t = (tid < 8) ? sh[tid] : 0.f;
#pragma unroll
        for (int o = 4; o; o >>= 1) t += __shfl_xor_sync(~0u, t, o);
        if (tid == 0) sh[0] = t;
    }
    __syncthreads();
    float inv = 1.0f / sh[0];
#pragma unroll
    for (int j = 0; j < 8; j++) {
        int k = tid + j * 256;
        rowp[k] = vals[j] * inv;
    }
}

// ---------------------------------------------------------------------------
extern "C" void kernel_launch(void* const* d_in, const int* in_sizes, int n_in,
                              void* d_out, int out_size) {
    const float* x     = (const float*)d_in[0];
    const float* q_w   = (const float*)d_in[1];
    const float* q_b   = (const float*)d_in[2];
    const float* k_w   = (const float*)d_in[3];
    const float* k_b   = (const float*)d_in[4];
    const float* ln_w  = (const float*)d_in[5];
    const float* ln_b  = (const float*)d_in[6];
    const float* embed = (const float*)d_in[7];
    const int*   pos   = (const int*)d_in[8];

    float* out   = (float*)d_out;
    float* q_out = out;
    float* k_out = out + QK_ELEMS;
    float* attn  = out + 2 * QK_ELEMS;

    cudaFuncSetAttribute(proj_cp_kernel, cudaFuncAttributeMaxDynamicSharedMemorySize, (int)GEMM_SMEM);
    cudaFuncSetAttribute(scores_cp_kernel, cudaFuncAttributeMaxDynamicSharedMemorySize, (int)GEMM_SMEM);

    ln_kernel<<<Mtot, 256>>>(x, ln_w, ln_b);

    dim3 gw((unsigned)(((size_t)Ee * Ee) / 1024), 2);   // 16384 x 2
    wconv_kernel<<<gw, 256>>>(q_w, k_w);

    dim3 gp(Mtot / BM, Ee / BN, 2);          // (32, 16, 2), x over M
    proj_cp_kernel<<<gp, 256, GEMM_SMEM>>>(q_b, k_b, embed, pos, q_out, k_out);

    dim3 g2(Ss / BN, Ss / BM, Bb * Hh);      // (8, 16, 32)
    scores_cp_kernel<<<g2, 256, GEMM_SMEM>>>(attn);

    softmax_kernel<<<Bb * Hh * Ss, 256>>>(attn);
}

// round 7
// speedup vs baseline: 1.2063x; 1.2063x over previous
#include <cuda_runtime.h>
#include <mma.h>
#include <cstdint>
#include <math.h>

using namespace nvcuda;

// Problem constants
constexpr int Bb = 2, Ss = 2048, Ee = 4096, Hh = 16, Dd = 256, Rr = 64;
constexpr int Mtot = Bb * Ss;                  // 4096
constexpr size_t QK_ELEMS = (size_t)Bb * Hh * Ss * Dd;   // 16777216

// GEMM tiling: CTA 128x128, 16 warps in 4x4, each warp 32x32
constexpr int BM = 128, BN = 128, BK = 32;
constexpr int NTHREADS = 512;
constexpr int ASTR = BK + 8;                             // 40 floats/row
constexpr uint32_t STAGE_A_BYTES = BM * ASTR * 4;        // 20480
constexpr uint32_t STAGE_BYTES = 2 * STAGE_A_BYTES;      // 40960
constexpr int NSTAGE = 3;
constexpr int CSTR = BN + 4;                             // 132
constexpr uint32_t GEMM_SMEM = NSTAGE * STAGE_BYTES;     // 122880 (Cs 128*132*4=67584 fits)

// Scratch
__device__ float g_xnorm[(size_t)Mtot * Ee];
__device__ float g_wq[(size_t)Ee * Ee];
__device__ float g_wk[(size_t)Ee * Ee];
__device__ float g_qr[QK_ELEMS];
__device__ float g_kr[QK_ELEMS];

__device__ __forceinline__ uint32_t smem_u32(const void* p) {
    uint32_t a;
    asm("{ .reg .u64 t; cvta.to.shared.u64 t, %1; cvt.u32.u64 %0, t; }" : "=r"(a) : "l"(p));
    return a;
}
__device__ __forceinline__ void cp16(uint32_t dst, const void* src) {
    asm volatile("cp.async.cg.shared.global [%0], [%1], 16;" :: "r"(dst), "l"(src));
}
#define CP_COMMIT() asm volatile("cp.async.commit_group;" ::: "memory")
#define CP_WAIT2()  asm volatile("cp.async.wait_group 2;" ::: "memory")

// ---------------------------------------------------------------------------
// LayerNorm (tf32-rounded output)
// ---------------------------------------------------------------------------
__global__ void __launch_bounds__(256) ln_kernel(const float* __restrict__ x,
                                                 const float* __restrict__ w,
                                                 const float* __restrict__ b) {
    int row = blockIdx.x;
    int tid = threadIdx.x;
    const float4* xr = reinterpret_cast<const float4*>(x + (size_t)row * Ee);

    float4 v[4];
    float sum = 0.f, ssq = 0.f;
#pragma unroll
    for (int j = 0; j < 4; j++) {
        v[j] = xr[tid + j * 256];
        sum += v[j].x + v[j].y + v[j].z + v[j].w;
        ssq += v[j].x * v[j].x + v[j].y * v[j].y + v[j].z * v[j].z + v[j].w * v[j].w;
    }
    __shared__ float s_sum[8], s_ssq[8];
#pragma unroll
    for (int o = 16; o; o >>= 1) {
        sum += __shfl_xor_sync(~0u, sum, o);
        ssq += __shfl_xor_sync(~0u, ssq, o);
    }
    if ((tid & 31) == 0) { s_sum[tid >> 5] = sum; s_ssq[tid >> 5] = ssq; }
    __syncthreads();
    if (tid < 32) {
        float ts = (tid < 8) ? s_sum[tid] : 0.f;
        float tq = (tid < 8) ? s_ssq[tid] : 0.f;
#pragma unroll
        for (int o = 4; o; o >>= 1) {
            ts += __shfl_xor_sync(~0u, ts, o);
            tq += __shfl_xor_sync(~0u, tq, o);
        }
        if (tid == 0) { s_sum[0] = ts; s_ssq[0] = tq; }
    }
    __syncthreads();
    float mean = s_sum[0] * (1.0f / Ee);
    float var = s_ssq[0] * (1.0f / Ee) - mean * mean;
    float rstd = rsqrtf(var + 1e-5f);

    const float4* wr = reinterpret_cast<const float4*>(w);
    const float4* br = reinterpret_cast<const float4*>(b);
    float4* outr = reinterpret_cast<float4*>(g_xnorm + (size_t)row * Ee);
#pragma unroll
    for (int j = 0; j < 4; j++) {
        int c = tid + j * 256;
        float4 wv = wr[c], bv = br[c], o;
        o.x = wmma::__float_to_tf32((v[j].x - mean) * rstd * wv.x + bv.x);
        o.y = wmma::__float_to_tf32((v[j].y - mean) * rstd * wv.y + bv.y);
        o.z = wmma::__float_to_tf32((v[j].z - mean) * rstd * wv.z + bv.z);
        o.w = wmma::__float_to_tf32((v[j].w - mean) * rstd * wv.w + bv.w);
        outr[c] = o;
    }
}

// ---------------------------------------------------------------------------
// Weight pre-rounding to tf32
// ---------------------------------------------------------------------------
__global__ void __launch_bounds__(256) wconv_kernel(const float* __restrict__ wq,
                                                    const float* __restrict__ wk) {
    const float* src = blockIdx.y ? wk : wq;
    float* dst = blockIdx.y ? g_wk : g_wq;
    size_t i = ((size_t)blockIdx.x * 256 + threadIdx.x) * 4;
    float4 v = *reinterpret_cast<const float4*>(src + i);
    v.x = wmma::__float_to_tf32(v.x);
    v.y = wmma::__float_to_tf32(v.y);
    v.z = wmma::__float_to_tf32(v.z);
    v.w = wmma::__float_to_tf32(v.w);
    *reinterpret_cast<float4*>(dst + i) = v;
}

// ---------------------------------------------------------------------------
// Pipelined tf32 wmma GEMM (NT), CTA 128x128, 16 warps, warp tile 32x32
// ---------------------------------------------------------------------------
using AccFrag = wmma::fragment<wmma::accumulator, 16, 16, 8, float>;

__device__ __forceinline__ void load_chunk(uint32_t sb, const char* Ab, const char* Bbp,
                                           size_t ldab, int kc, int buf, int tid) {
    uint32_t stA = sb + buf * STAGE_BYTES;
    uint32_t stB = stA + STAGE_A_BYTES;
    const char* Ap = Ab + (size_t)kc * (BK * 4);
    const char* Bp = Bbp + (size_t)kc * (BK * 4);
#pragma unroll
    for (int l = 0; l < 2; l++) {
        int idx = tid + l * NTHREADS;    // 0..1023
        int r = idx >> 3, cb = (idx & 7) << 4;
        cp16(stA + r * (ASTR * 4) + cb, Ap + (size_t)r * ldab + cb);
        cp16(stB + r * (ASTR * 4) + cb, Bp + (size_t)r * ldab + cb);
    }
}

template <int NCHUNK>
__device__ __forceinline__ void gemm_pipe(const char* Ab, const char* Bbp, size_t ldab,
                                          char* smem, AccFrag acc[2][2]) {
    uint32_t sb = smem_u32(smem);
    int tid = threadIdx.x;
    int warp = tid >> 5;
    int wm = warp & 3;        // 4 along M, 32 rows each
    int wn = warp >> 2;       // 4 along N, 32 cols each

    load_chunk(sb, Ab, Bbp, ldab, 0, 0, tid);
    CP_COMMIT();
    if (NCHUNK > 1) load_chunk(sb, Ab, Bbp, ldab, 1, 1, tid);
    CP_COMMIT();

    for (int k = 0; k < NCHUNK; k++) {
        if (k + 2 < NCHUNK) load_chunk(sb, Ab, Bbp, ldab, k + 2, (k + 2) % NSTAGE, tid);
        CP_COMMIT();
        CP_WAIT2();
        __syncthreads();

        float* As = reinterpret_cast<float*>(smem + (k % NSTAGE) * STAGE_BYTES);
        float* Bs = As + BM * ASTR;
#pragma unroll
        for (int kk = 0; kk < BK; kk += 8) {
            wmma::fragment<wmma::matrix_a, 16, 16, 8, wmma::precision::tf32, wmma::row_major> af[2];
            wmma::fragment<wmma::matrix_b, 16, 16, 8, wmma::precision::tf32, wmma::col_major> bf[2];
#pragma unroll
            for (int i = 0; i < 2; i++)
                wmma::load_matrix_sync(af[i], As + (wm * 32 + i * 16) * ASTR + kk, ASTR);
#pragma unroll
            for (int j = 0; j < 2; j++)
                wmma::load_matrix_sync(bf[j], Bs + (wn * 32 + j * 16) * ASTR + kk, ASTR);
#pragma unroll
            for (int i = 0; i < 2; i++)
#pragma unroll
                for (int j = 0; j < 2; j++)
                    wmma::mma_sync(acc[i][j], af[i], bf[j], acc[i][j]);
        }
        __syncthreads();
    }
}

__device__ __forceinline__ void store_acc(float* Cs, AccFrag acc[2][2]) {
    int warp = threadIdx.x >> 5;
    int wm = warp & 3, wn = warp >> 2;
#pragma unroll
    for (int i = 0; i < 2; i++)
#pragma unroll
        for (int j = 0; j < 2; j++)
            wmma::store_matrix_sync(Cs + (wm * 32 + i * 16) * CSTR + wn * 32 + j * 16,
                                    acc[i][j], CSTR, wmma::mem_row_major);
}

// ---------------------------------------------------------------------------
// Projection GEMM + bias + RoPE; writes fp32 q/k and tf32-rounded copies
// ---------------------------------------------------------------------------
__global__ void __launch_bounds__(NTHREADS, 1) proj_cp_kernel(
    const float* __restrict__ bq, const float* __restrict__ bk,
    const float* __restrict__ embed, const int* __restrict__ posids,
    float* __restrict__ qout, float* __restrict__ kout)
{
    extern __shared__ __align__(128) char smem[];
    int z = blockIdx.z;
    const float* W    = z ? g_wk : g_wq;
    const float* bias = z ? bk : bq;
    float* outp       = z ? kout : qout;
    float* routp      = z ? g_kr : g_qr;
    const int m0 = blockIdx.x * BM;   // x fastest: consecutive CTAs share the weight panel
    const int n0 = blockIdx.y * BN;

    AccFrag acc[2][2];
#pragma unroll
    for (int i = 0; i < 2; i++)
#pragma unroll
        for (int j = 0; j < 2; j++)
            wmma::fill_fragment(acc[i][j], 0.f);

    gemm_pipe<Ee / BK>(reinterpret_cast<const char*>(g_xnorm + (size_t)m0 * Ee),
                       reinterpret_cast<const char*>(W + (size_t)n0 * Ee),
                       (size_t)Ee * 4, smem, acc);

    float* Cs = reinterpret_cast<float*>(smem);
    store_acc(Cs, acc);
    __syncthreads();

    int tid = threadIdx.x;
#pragma unroll 4
    for (int i = 0; i < 16; i++) {
        int it = tid + i * NTHREADS;     // 0..8191 over 128x64 pairs
        int r = it >> 6;                 // 0..127
        int pc = it & 63;                // pair col
        int c = pc << 1;
        int m = m0 + r, f = n0 + c;
        float v0 = Cs[r * CSTR + c] + bias[f];
        float v1 = Cs[r * CSTR + c + 1] + bias[f + 1];
        int d = f & 255;
        if (d < Rr) {
            int pos = posids[m];
            int i2 = d >> 1;
            float sn = embed[pos * Rr + i2];
            float co = embed[pos * Rr + 32 + i2];
            float o0 = v0 * co - v1 * sn;
            float o1 = v1 * co + v0 * sn;
            v0 = o0; v1 = o1;
        }
        int b_ = m >> 11, s_ = m & 2047, h_ = f >> 8;
        size_t off = ((size_t)(b_ * Hh + h_) * Ss + s_) * Dd + d;
        *reinterpret_cast<float2*>(outp + off) = make_float2(v0, v1);
        *reinterpret_cast<float2*>(routp + off) =
            make_float2(wmma::__float_to_tf32(v0), wmma::__float_to_tf32(v1));
    }
}

// ---------------------------------------------------------------------------
// Scores GEMM: scores = Qr.Kr^T / 16, causal tile skip
// ---------------------------------------------------------------------------
__global__ void __launch_bounds__(NTHREADS, 1) scores_cp_kernel(float* __restrict__ attn)
{
    int kt = blockIdx.x, qt = blockIdx.y, bh = blockIdx.z;
    if (kt > qt) return;

    extern __shared__ __align__(128) char smem[];
    int m0 = qt * BM, n0 = kt * BN;
    const float* Q = g_qr + (size_t)bh * Ss * Dd;
    const float* Kv = g_kr + (size_t)bh * Ss * Dd;

    AccFrag acc[2][2];
#pragma unroll
    for (int i = 0; i < 2; i++)
#pragma unroll
        for (int j = 0; j < 2; j++)
            wmma::fill_fragment(acc[i][j], 0.f);

    gemm_pipe<Dd / BK>(reinterpret_cast<const char*>(Q + (size_t)m0 * Dd),
                       reinterpret_cast<const char*>(Kv + (size_t)n0 * Dd),
                       (size_t)Dd * 4, smem, acc);

    float* Cs = reinterpret_cast<float*>(smem);
    store_acc(Cs, acc);
    __syncthreads();

    float* out_base = attn + (size_t)bh * Ss * Ss;
#pragma unroll
    for (int i = 0; i < 8; i++) {
        int it = threadIdx.x + i * NTHREADS;   // 0..4095 float4s over 128x128
        int r = it >> 5;                       // 0..127
        int c4 = (it & 31) << 2;               // 0..124 step 4
        float4 v = *reinterpret_cast<const float4*>(Cs + r * CSTR + c4);
        v.x *= 0.0625f; v.y *= 0.0625f; v.z *= 0.0625f; v.w *= 0.0625f;
        *reinterpret_cast<float4*>(out_base + (size_t)(m0 + r) * Ss + n0 + c4) = v;
    }
}

// ---------------------------------------------------------------------------
// In-place masked softmax
// ---------------------------------------------------------------------------
__global__ void __launch_bounds__(256) softmax_kernel(float* __restrict__ attn) {
    int row = blockIdx.x;
    int q = row & 2047;
    int nv = q + 1;
    float* rowp = attn + (size_t)row * Ss;
    int tid = threadIdx.x;

    float vals[8];
    float mx = -INFINITY;
#pragma unroll
    for (int j = 0; j < 8; j++) {
        int k = tid + j * 256;
        float v = (k < nv) ? rowp[k] : -INFINITY;
        vals[j] = v;
        mx = fmaxf(mx, v);
    }
    __shared__ float sh[8];
#pragma unroll
    for (int o = 16; o; o >>= 1) mx = fmaxf(mx, __shfl_xor_sync(~0u, mx, o));
    if ((tid & 31) == 0) sh[tid >> 5] = mx;
    __syncthreads();
    if (tid < 32) {
        float t = (tid < 8) ? sh[tid] : -INFINITY;
#pragma unroll
        for (int o = 4; o; o >>= 1) t = fmaxf(t, __shfl_xor_sync(~0u, t, o));
        if (tid == 0) sh[0] = t;
    }
    __syncthreads();
    float M = sh[0];
    __syncthreads();

    float sum = 0.f;
#pragma unroll
    for (int j = 0; j < 8; j++) {
        int k = tid + j * 256;
        float e = (k < nv) ? expf(vals[j] - M) : 0.f;
        vals[j] = e;
        sum += e;
    }
#pragma unroll
    for (int o = 16; o; o >>= 1) sum += __shfl_xor_sync(~0u, sum, o);
    if ((tid & 31) == 0) sh[tid >> 5] = sum;
    __syncthreads();
    if (tid < 32) {
        float t = (tid < 8) ? sh[tid] : 0.f;
#pragma unroll
        for (int o = 4; o; o >>= 1) t += __shfl_xor_sync(~0u, t, o);
        if (tid == 0) sh[0] = t;
    }
    __syncthreads();
    float inv = 1.0f / sh[0];
#pragma unroll
    for (int j = 0; j < 8; j++) {
        int k = tid + j * 256;
        rowp[k] = vals[j] * inv;
    }
}

// ---------------------------------------------------------------------------
extern "C" void kernel_launch(void* const* d_in, const int* in_sizes, int n_in,
                              void* d_out, int out_size) {
    const float* x     = (const float*)d_in[0];
    const float* q_w   = (const float*)d_in[1];
    const float* q_b   = (const float*)d_in[2];
    const float* k_w   = (const float*)d_in[3];
    const float* k_b   = (const float*)d_in[4];
    const float* ln_w  = (const float*)d_in[5];
    const float* ln_b  = (const float*)d_in[6];
    const float* embed = (const float*)d_in[7];
    const int*   pos   = (const int*)d_in[8];

    float* out   = (float*)d_out;
    float* q_out = out;
    float* k_out = out + QK_ELEMS;
    float* attn  = out + 2 * QK_ELEMS;

    cudaFuncSetAttribute(proj_cp_kernel, cudaFuncAttributeMaxDynamicSharedMemorySize, (int)GEMM_SMEM);
    cudaFuncSetAttribute(scores_cp_kernel, cudaFuncAttributeMaxDynamicSharedMemorySize, (int)GEMM_SMEM);

    ln_kernel<<<Mtot, 256>>>(x, ln_w, ln_b);

    dim3 gw((unsigned)(((size_t)Ee * Ee) / 1024), 2);   // 16384 x 2
    wconv_kernel<<<gw, 256>>>(q_w, k_w);

    dim3 gp(Mtot / BM, Ee / BN, 2);          // (32, 32, 2), x over M
    proj_cp_kernel<<<gp, NTHREADS, GEMM_SMEM>>>(q_b, k_b, embed, pos, q_out, k_out);

    dim3 g2(Ss / BN, Ss / BM, Bb * Hh);      // (16, 16, 32)
    scores_cp_kernel<<<g2, NTHREADS, GEMM_SMEM>>>(attn);

    softmax_kernel<<<Bb * Hh * Ss, 256>>>(attn);
}

// round 8
// speedup vs baseline: 1.5348x; 1.2723x over previous
#include <cuda_runtime.h>
#include <mma.h>
#include <cstdint>
#include <math.h>

using namespace nvcuda;

// Problem constants
constexpr int Bb = 2, Ss = 2048, Ee = 4096, Hh = 16, Dd = 256, Rr = 64;
constexpr int Mtot = Bb * Ss;                  // 4096
constexpr size_t QK_ELEMS = (size_t)Bb * Hh * Ss * Dd;   // 16777216

// GEMM tiling: CTA 128x128, 8 warps in 2x4, warp tile 64x32, 2-stage pipeline
constexpr int BM = 128, BN = 128, BK = 32;
constexpr int NTHREADS = 256;
constexpr int ASTR = BK + 8;                             // 40 floats/row
constexpr uint32_t STAGE_A_BYTES = BM * ASTR * 4;        // 20480
constexpr uint32_t STAGE_BYTES = 2 * STAGE_A_BYTES;      // 40960
constexpr int NSTAGE = 2;
constexpr int CSTR = BN + 4;                             // 132
constexpr uint32_t GEMM_SMEM = NSTAGE * STAGE_BYTES;     // 81920 (Cs 67584 fits; 2 CTAs/SM)

// Scratch
__device__ float g_xnorm[(size_t)Mtot * Ee];
__device__ float g_wq[(size_t)Ee * Ee];
__device__ float g_wk[(size_t)Ee * Ee];
__device__ float g_qr[QK_ELEMS];
__device__ float g_kr[QK_ELEMS];

__device__ __forceinline__ uint32_t smem_u32(const void* p) {
    uint32_t a;
    asm("{ .reg .u64 t; cvta.to.shared.u64 t, %1; cvt.u32.u64 %0, t; }" : "=r"(a) : "l"(p));
    return a;
}
__device__ __forceinline__ void cp16(uint32_t dst, const void* src) {
    asm volatile("cp.async.cg.shared.global [%0], [%1], 16;" :: "r"(dst), "l"(src));
}
#define CP_COMMIT() asm volatile("cp.async.commit_group;" ::: "memory")
#define CP_WAIT1()  asm volatile("cp.async.wait_group 1;" ::: "memory")

// ---------------------------------------------------------------------------
// LayerNorm (tf32-rounded output)
// ---------------------------------------------------------------------------
__global__ void __launch_bounds__(256) ln_kernel(const float* __restrict__ x,
                                                 const float* __restrict__ w,
                                                 const float* __restrict__ b) {
    int row = blockIdx.x;
    int tid = threadIdx.x;
    const float4* xr = reinterpret_cast<const float4*>(x + (size_t)row * Ee);

    float4 v[4];
    float sum = 0.f, ssq = 0.f;
#pragma unroll
    for (int j = 0; j < 4; j++) {
        v[j] = xr[tid + j * 256];
        sum += v[j].x + v[j].y + v[j].z + v[j].w;
        ssq += v[j].x * v[j].x + v[j].y * v[j].y + v[j].z * v[j].z + v[j].w * v[j].w;
    }
    __shared__ float s_sum[8], s_ssq[8];
#pragma unroll
    for (int o = 16; o; o >>= 1) {
        sum += __shfl_xor_sync(~0u, sum, o);
        ssq += __shfl_xor_sync(~0u, ssq, o);
    }
    if ((tid & 31) == 0) { s_sum[tid >> 5] = sum; s_ssq[tid >> 5] = ssq; }
    __syncthreads();
    if (tid < 32) {
        float ts = (tid < 8) ? s_sum[tid] : 0.f;
        float tq = (tid < 8) ? s_ssq[tid] : 0.f;
#pragma unroll
        for (int o = 4; o; o >>= 1) {
            ts += __shfl_xor_sync(~0u, ts, o);
            tq += __shfl_xor_sync(~0u, tq, o);
        }
        if (tid == 0) { s_sum[0] = ts; s_ssq[0] = tq; }
    }
    __syncthreads();
    float mean = s_sum[0] * (1.0f / Ee);
    float var = s_ssq[0] * (1.0f / Ee) - mean * mean;
    float rstd = rsqrtf(var + 1e-5f);

    const float4* wr = reinterpret_cast<const float4*>(w);
    const float4* br = reinterpret_cast<const float4*>(b);
    float4* outr = reinterpret_cast<float4*>(g_xnorm + (size_t)row * Ee);
#pragma unroll
    for (int j = 0; j < 4; j++) {
        int c = tid + j * 256;
        float4 wv = wr[c], bv = br[c], o;
        o.x = wmma::__float_to_tf32((v[j].x - mean) * rstd * wv.x + bv.x);
        o.y = wmma::__float_to_tf32((v[j].y - mean) * rstd * wv.y + bv.y);
        o.z = wmma::__float_to_tf32((v[j].z - mean) * rstd * wv.z + bv.z);
        o.w = wmma::__float_to_tf32((v[j].w - mean) * rstd * wv.w + bv.w);
        outr[c] = o;
    }
}

// ---------------------------------------------------------------------------
// Weight pre-rounding to tf32
// ---------------------------------------------------------------------------
__global__ void __launch_bounds__(256) wconv_kernel(const float* __restrict__ wq,
                                                    const float* __restrict__ wk) {
    const float* src = blockIdx.y ? wk : wq;
    float* dst = blockIdx.y ? g_wk : g_wq;
    size_t i = ((size_t)blockIdx.x * 256 + threadIdx.x) * 4;
    float4 v = *reinterpret_cast<const float4*>(src + i);
    v.x = wmma::__float_to_tf32(v.x);
    v.y = wmma::__float_to_tf32(v.y);
    v.z = wmma::__float_to_tf32(v.z);
    v.w = wmma::__float_to_tf32(v.w);
    *reinterpret_cast<float4*>(dst + i) = v;
}

// ---------------------------------------------------------------------------
// Pipelined tf32 wmma GEMM (NT), CTA 128x128, 8 warps, warp tile 64x32
// 2-stage cp.async pipeline (enables 2 CTAs/SM)
// ---------------------------------------------------------------------------
using AccFrag = wmma::fragment<wmma::accumulator, 16, 16, 8, float>;

__device__ __forceinline__ void load_chunk(uint32_t sb, const char* Ab, const char* Bbp,
                                           size_t ldab, int kc, int buf, int tid) {
    uint32_t stA = sb + buf * STAGE_BYTES;
    uint32_t stB = stA + STAGE_A_BYTES;
    const char* Ap = Ab + (size_t)kc * (BK * 4);
    const char* Bp = Bbp + (size_t)kc * (BK * 4);
#pragma unroll
    for (int l = 0; l < 4; l++) {
        int idx = tid + l * NTHREADS;    // 0..1023
        int r = idx >> 3, cb = (idx & 7) << 4;
        cp16(stA + r * (ASTR * 4) + cb, Ap + (size_t)r * ldab + cb);
        cp16(stB + r * (ASTR * 4) + cb, Bp + (size_t)r * ldab + cb);
    }
}

template <int NCHUNK>
__device__ __forceinline__ void gemm_pipe(const char* Ab, const char* Bbp, size_t ldab,
                                          char* smem, AccFrag acc[4][2]) {
    uint32_t sb = smem_u32(smem);
    int tid = threadIdx.x;
    int warp = tid >> 5;
    int wm = warp & 1;        // 2 along M, 64 rows each
    int wn = warp >> 1;       // 4 along N, 32 cols each

    load_chunk(sb, Ab, Bbp, ldab, 0, 0, tid);
    CP_COMMIT();

    for (int k = 0; k < NCHUNK; k++) {
        if (k + 1 < NCHUNK) load_chunk(sb, Ab, Bbp, ldab, k + 1, (k + 1) & 1, tid);
        CP_COMMIT();
        CP_WAIT1();               // chunk k resident; chunk k+1 may still fly
        __syncthreads();

        float* As = reinterpret_cast<float*>(smem + (k & 1) * STAGE_BYTES);
        float* Bs = As + BM * ASTR;
#pragma unroll
        for (int kk = 0; kk < BK; kk += 8) {
            wmma::fragment<wmma::matrix_a, 16, 16, 8, wmma::precision::tf32, wmma::row_major> af[4];
            wmma::fragment<wmma::matrix_b, 16, 16, 8, wmma::precision::tf32, wmma::col_major> bf[2];
#pragma unroll
            for (int i = 0; i < 4; i++)
                wmma::load_matrix_sync(af[i], As + (wm * 64 + i * 16) * ASTR + kk, ASTR);
#pragma unroll
            for (int j = 0; j < 2; j++)
                wmma::load_matrix_sync(bf[j], Bs + (wn * 32 + j * 16) * ASTR + kk, ASTR);
#pragma unroll
            for (int i = 0; i < 4; i++)
#pragma unroll
                for (int j = 0; j < 2; j++)
                    wmma::mma_sync(acc[i][j], af[i], bf[j], acc[i][j]);
        }
        __syncthreads();
    }
}

__device__ __forceinline__ void store_acc(float* Cs, AccFrag acc[4][2]) {
    int warp = threadIdx.x >> 5;
    int wm = warp & 1, wn = warp >> 1;
#pragma unroll
    for (int i = 0; i < 4; i++)
#pragma unroll
        for (int j = 0; j < 2; j++)
            wmma::store_matrix_sync(Cs + (wm * 64 + i * 16) * CSTR + wn * 32 + j * 16,
                                    acc[i][j], CSTR, wmma::mem_row_major);
}

// ---------------------------------------------------------------------------
// Projection GEMM + bias + RoPE; writes fp32 q/k and tf32-rounded copies
// ---------------------------------------------------------------------------
__global__ void __launch_bounds__(NTHREADS, 2) proj_cp_kernel(
    const float* __restrict__ bq, const float* __restrict__ bk,
    const float* __restrict__ embed, const int* __restrict__ posids,
    float* __restrict__ qout, float* __restrict__ kout)
{
    extern __shared__ __align__(128) char smem[];
    int z = blockIdx.z;
    const float* W    = z ? g_wk : g_wq;
    const float* bias = z ? bk : bq;
    float* outp       = z ? kout : qout;
    float* routp      = z ? g_kr : g_qr;
    const int m0 = blockIdx.x * BM;   // x fastest: consecutive CTAs share the weight panel
    const int n0 = blockIdx.y * BN;

    AccFrag acc[4][2];
#pragma unroll
    for (int i = 0; i < 4; i++)
#pragma unroll
        for (int j = 0; j < 2; j++)
            wmma::fill_fragment(acc[i][j], 0.f);

    gemm_pipe<Ee / BK>(reinterpret_cast<const char*>(g_xnorm + (size_t)m0 * Ee),
                       reinterpret_cast<const char*>(W + (size_t)n0 * Ee),
                       (size_t)Ee * 4, smem, acc);

    float* Cs = reinterpret_cast<float*>(smem);
    store_acc(Cs, acc);
    __syncthreads();

    int tid = threadIdx.x;
#pragma unroll 4
    for (int i = 0; i < 32; i++) {
        int it = tid + i * NTHREADS;     // 0..8191 over 128x64 pairs
        int r = it >> 6;                 // 0..127
        int pc = it & 63;                // pair col
        int c = pc << 1;
        int m = m0 + r, f = n0 + c;
        float v0 = Cs[r * CSTR + c] + bias[f];
        float v1 = Cs[r * CSTR + c + 1] + bias[f + 1];
        int d = f & 255;
        if (d < Rr) {
            int pos = posids[m];
            int i2 = d >> 1;
            float sn = embed[pos * Rr + i2];
            float co = embed[pos * Rr + 32 + i2];
            float o0 = v0 * co - v1 * sn;
            float o1 = v1 * co + v0 * sn;
            v0 = o0; v1 = o1;
        }
        int b_ = m >> 11, s_ = m & 2047, h_ = f >> 8;
        size_t off = ((size_t)(b_ * Hh + h_) * Ss + s_) * Dd + d;
        *reinterpret_cast<float2*>(outp + off) = make_float2(v0, v1);
        *reinterpret_cast<float2*>(routp + off) =
            make_float2(wmma::__float_to_tf32(v0), wmma::__float_to_tf32(v1));
    }
}

// ---------------------------------------------------------------------------
// Scores GEMM: scores = Qr.Kr^T / 16, causal tile skip
// ---------------------------------------------------------------------------
__global__ void __launch_bounds__(NTHREADS, 2) scores_cp_kernel(float* __restrict__ attn)
{
    int kt = blockIdx.x, qt = blockIdx.y, bh = blockIdx.z;
    if (kt > qt) return;

    extern __shared__ __align__(128) char smem[];
    int m0 = qt * BM, n0 = kt * BN;
    const float* Q = g_qr + (size_t)bh * Ss * Dd;
    const float* Kv = g_kr + (size_t)bh * Ss * Dd;

    AccFrag acc[4][2];
#pragma unroll
    for (int i = 0; i < 4; i++)
#pragma unroll
        for (int j = 0; j < 2; j++)
            wmma::fill_fragment(acc[i][j], 0.f);

    gemm_pipe<Dd / BK>(reinterpret_cast<const char*>(Q + (size_t)m0 * Dd),
                       reinterpret_cast<const char*>(Kv + (size_t)n0 * Dd),
                       (size_t)Dd * 4, smem, acc);

    float* Cs = reinterpret_cast<float*>(smem);
    store_acc(Cs, acc);
    __syncthreads();

    float* out_base = attn + (size_t)bh * Ss * Ss;
#pragma unroll
    for (int i = 0; i < 16; i++) {
        int it = threadIdx.x + i * NTHREADS;   // 0..4095 float4s over 128x128
        int r = it >> 5;                       // 0..127
        int c4 = (it & 31) << 2;               // 0..124 step 4
        float4 v = *reinterpret_cast<const float4*>(Cs + r * CSTR + c4);
        v.x *= 0.0625f; v.y *= 0.0625f; v.z *= 0.0625f; v.w *= 0.0625f;
        *reinterpret_cast<float4*>(out_base + (size_t)(m0 + r) * Ss + n0 + c4) = v;
    }
}

// ---------------------------------------------------------------------------
// In-place masked softmax
// ---------------------------------------------------------------------------
__global__ void __launch_bounds__(256) softmax_kernel(float* __restrict__ attn) {
    int row = blockIdx.x;
    int q = row & 2047;
    int nv = q + 1;
    float* rowp = attn + (size_t)row * Ss;
    int tid = threadIdx.x;

    float vals[8];
    float mx = -INFINITY;
#pragma unroll
    for (int j = 0; j < 8; j++) {
        int k = tid + j * 256;
        float v = (k < nv) ? rowp[k] : -INFINITY;
        vals[j] = v;
        mx = fmaxf(mx, v);
    }
    __shared__ float sh[8];
#pragma unroll
    for (int o = 16; o; o >>= 1) mx = fmaxf(mx, __shfl_xor_sync(~0u, mx, o));
    if ((tid & 31) == 0) sh[tid >> 5] = mx;
    __syncthreads();
    if (tid < 32) {
        float t = (tid < 8) ? sh[tid] : -INFINITY;
#pragma unroll
        for (int o = 4; o; o >>= 1) t = fmaxf(t, __shfl_xor_sync(~0u, t, o));
        if (tid == 0) sh[0] = t;
    }
    __syncthreads();
    float M = sh[0];
    __syncthreads();

    float sum = 0.f;
#pragma unroll
    for (int j = 0; j < 8; j++) {
        int k = tid + j * 256;
        float e = (k < nv) ? expf(vals[j] - M) : 0.f;
        vals[j] = e;
        sum += e;
    }
#pragma unroll
    for (int o = 16; o; o >>= 1) sum += __shfl_xor_sync(~0u, sum, o);
    if ((tid & 31) == 0) sh[tid >> 5] = sum;
    __syncthreads();
    if (tid < 32) {
        float t = (tid < 8) ? sh[tid] : 0.f;
#pragma unroll
        for (int o = 4; o; o >>= 1) t += __shfl_xor_sync(~0u, t, o);
        if (tid == 0) sh[0] = t;
    }
    __syncthreads();
    float inv = 1.0f / sh[0];
#pragma unroll
    for (int j = 0; j < 8; j++) {
        int k = tid + j * 256;
        rowp[k] = vals[j] * inv;
    }
}

// ---------------------------------------------------------------------------
extern "C" void kernel_launch(void* const* d_in, const int* in_sizes, int n_in,
                              void* d_out, int out_size) {
    const float* x     = (const float*)d_in[0];
    const float* q_w   = (const float*)d_in[1];
    const float* q_b   = (const float*)d_in[2];
    const float* k_w   = (const float*)d_in[3];
    const float* k_b   = (const float*)d_in[4];
    const float* ln_w  = (const float*)d_in[5];
    const float* ln_b  = (const float*)d_in[6];
    const float* embed = (const float*)d_in[7];
    const int*   pos   = (const int*)d_in[8];

    float* out   = (float*)d_out;
    float* q_out = out;
    float* k_out = out + QK_ELEMS;
    float* attn  = out + 2 * QK_ELEMS;

    cudaFuncSetAttribute(proj_cp_kernel, cudaFuncAttributeMaxDynamicSharedMemorySize, (int)GEMM_SMEM);
    cudaFuncSetAttribute(scores_cp_kernel, cudaFuncAttributeMaxDynamicSharedMemorySize, (int)GEMM_SMEM);

    ln_kernel<<<Mtot, 256>>>(x, ln_w, ln_b);

    dim3 gw((unsigned)(((size_t)Ee * Ee) / 1024), 2);   // 16384 x 2
    wconv_kernel<<<gw, 256>>>(q_w, k_w);

    dim3 gp(Mtot / BM, Ee / BN, 2);          // (32, 32, 2), x over M
    proj_cp_kernel<<<gp, NTHREADS, GEMM_SMEM>>>(q_b, k_b, embed, pos, q_out, k_out);

    dim3 g2(Ss / BN, Ss / BM, Bb * Hh);      // (16, 16, 32)
    scores_cp_kernel<<<g2, NTHREADS, GEMM_SMEM>>>(attn);

    softmax_kernel<<<Bb * Hh * Ss, 256>>>(attn);
}

// round 9
// speedup vs baseline: 5.4365x; 3.5422x over previous
#include <cuda_runtime.h>
#include <mma.h>
#include <cuda_fp16.h>
#include <cstdint>
#include <math.h>

using namespace nvcuda;

// Problem constants
constexpr int Bb = 2, Ss = 2048, Ee = 4096, Hh = 16, Dd = 256, Rr = 64;
constexpr int Mtot = Bb * Ss;                  // 4096
constexpr size_t QK_ELEMS = (size_t)Bb * Hh * Ss * Dd;   // 16777216

// GEMM tiling: CTA 128x128, 8 warps in 2x4, warp tile 64x32, fp16 inputs
constexpr int BM = 128, BN = 128, BK = 64;     // BK=64 halves = 128 bytes/row
constexpr int NTHREADS = 256;
constexpr int ASTR = BK + 8;                   // 72 halves = 144 bytes/row (16B-aligned)
constexpr uint32_t STAGE_A_BYTES = BM * ASTR * 2;        // 18432
constexpr uint32_t STAGE_BYTES = 2 * STAGE_A_BYTES;      // 36864
constexpr int NSTAGE = 2;
constexpr int CSTR = BN + 4;                   // 132
constexpr uint32_t GEMM_SMEM = NSTAGE * STAGE_BYTES;     // 73728 (Cs 128*132*4=67584 fits; 2 CTAs/SM)

// Scratch (fp16 GEMM operands)
__device__ __half g_xnorm[(size_t)Mtot * Ee];
__device__ __half g_wq[(size_t)Ee * Ee];
__device__ __half g_wk[(size_t)Ee * Ee];
__device__ __half g_qr[QK_ELEMS];
__device__ __half g_kr[QK_ELEMS];

__device__ __forceinline__ uint32_t smem_u32(const void* p) {
    uint32_t a;
    asm("{ .reg .u64 t; cvta.to.shared.u64 t, %1; cvt.u32.u64 %0, t; }" : "=r"(a) : "l"(p));
    return a;
}
__device__ __forceinline__ void cp16(uint32_t dst, const void* src) {
    asm volatile("cp.async.cg.shared.global [%0], [%1], 16;" :: "r"(dst), "l"(src));
}
#define CP_COMMIT() asm volatile("cp.async.commit_group;" ::: "memory")
#define CP_WAIT1()  asm volatile("cp.async.wait_group 1;" ::: "memory")

// ---------------------------------------------------------------------------
// LayerNorm -> fp16 g_xnorm
// ---------------------------------------------------------------------------
__global__ void __launch_bounds__(256) ln_kernel(const float* __restrict__ x,
                                                 const float* __restrict__ w,
                                                 const float* __restrict__ b) {
    int row = blockIdx.x;
    int tid = threadIdx.x;
    const float4* xr = reinterpret_cast<const float4*>(x + (size_t)row * Ee);

    float4 v[4];
    float sum = 0.f, ssq = 0.f;
#pragma unroll
    for (int j = 0; j < 4; j++) {
        v[j] = xr[tid + j * 256];
        sum += v[j].x + v[j].y + v[j].z + v[j].w;
        ssq += v[j].x * v[j].x + v[j].y * v[j].y + v[j].z * v[j].z + v[j].w * v[j].w;
    }
    __shared__ float s_sum[8], s_ssq[8];
#pragma unroll
    for (int o = 16; o; o >>= 1) {
        sum += __shfl_xor_sync(~0u, sum, o);
        ssq += __shfl_xor_sync(~0u, ssq, o);
    }
    if ((tid & 31) == 0) { s_sum[tid >> 5] = sum; s_ssq[tid >> 5] = ssq; }
    __syncthreads();
    if (tid < 32) {
        float ts = (tid < 8) ? s_sum[tid] : 0.f;
        float tq = (tid < 8) ? s_ssq[tid] : 0.f;
#pragma unroll
        for (int o = 4; o; o >>= 1) {
            ts += __shfl_xor_sync(~0u, ts, o);
            tq += __shfl_xor_sync(~0u, tq, o);
        }
        if (tid == 0) { s_sum[0] = ts; s_ssq[0] = tq; }
    }
    __syncthreads();
    float mean = s_sum[0] * (1.0f / Ee);
    float var = s_ssq[0] * (1.0f / Ee) - mean * mean;
    float rstd = rsqrtf(var + 1e-5f);

    const float4* wr = reinterpret_cast<const float4*>(w);
    const float4* br = reinterpret_cast<const float4*>(b);
    __half2* outr = reinterpret_cast<__half2*>(g_xnorm + (size_t)row * Ee);
#pragma unroll
    for (int j = 0; j < 4; j++) {
        int c = tid + j * 256;
        float4 wv = wr[c], bv = br[c];
        float o0 = (v[j].x - mean) * rstd * wv.x + bv.x;
        float o1 = (v[j].y - mean) * rstd * wv.y + bv.y;
        float o2 = (v[j].z - mean) * rstd * wv.z + bv.z;
        float o3 = (v[j].w - mean) * rstd * wv.w + bv.w;
        outr[c * 2]     = __floats2half2_rn(o0, o1);
        outr[c * 2 + 1] = __floats2half2_rn(o2, o3);
    }
}

// ---------------------------------------------------------------------------
// Weight conversion fp32 -> fp16
// ---------------------------------------------------------------------------
__global__ void __launch_bounds__(256) wconv_kernel(const float* __restrict__ wq,
                                                    const float* __restrict__ wk) {
    const float* src = blockIdx.y ? wk : wq;
    __half* dst = blockIdx.y ? g_wk : g_wq;
    size_t i = ((size_t)blockIdx.x * 256 + threadIdx.x) * 4;
    float4 v = *reinterpret_cast<const float4*>(src + i);
    __half2* d2 = reinterpret_cast<__half2*>(dst + i);
    d2[0] = __floats2half2_rn(v.x, v.y);
    d2[1] = __floats2half2_rn(v.z, v.w);
}

// ---------------------------------------------------------------------------
// Pipelined fp16 wmma GEMM (NT), CTA 128x128, 8 warps, warp tile 64x32
// ---------------------------------------------------------------------------
using AccFrag = wmma::fragment<wmma::accumulator, 16, 16, 16, float>;

__device__ __forceinline__ void load_chunk(uint32_t sb, const char* Ab, const char* Bbp,
                                           size_t ldab, int kc, int buf, int tid) {
    uint32_t stA = sb + buf * STAGE_BYTES;
    uint32_t stB = stA + STAGE_A_BYTES;
    const char* Ap = Ab + (size_t)kc * (BK * 2);   // chunk offset: 128 bytes
    const char* Bp = Bbp + (size_t)kc * (BK * 2);
#pragma unroll
    for (int l = 0; l < 4; l++) {
        int idx = tid + l * NTHREADS;    // 0..1023
        int r = idx >> 3, cb = (idx & 7) << 4;     // row, byte-chunk 0..112
        cp16(stA + r * (ASTR * 2) + cb, Ap + (size_t)r * ldab + cb);
        cp16(stB + r * (ASTR * 2) + cb, Bp + (size_t)r * ldab + cb);
    }
}

template <int NCHUNK>
__device__ __forceinline__ void gemm_pipe(const char* Ab, const char* Bbp, size_t ldab,
                                          char* smem, AccFrag acc[4][2]) {
    uint32_t sb = smem_u32(smem);
    int tid = threadIdx.x;
    int warp = tid >> 5;
    int wm = warp & 1;        // 2 along M, 64 rows each
    int wn = warp >> 1;       // 4 along N, 32 cols each

    load_chunk(sb, Ab, Bbp, ldab, 0, 0, tid);
    CP_COMMIT();

    for (int k = 0; k < NCHUNK; k++) {
        if (k + 1 < NCHUNK) load_chunk(sb, Ab, Bbp, ldab, k + 1, (k + 1) & 1, tid);
        CP_COMMIT();
        CP_WAIT1();
        __syncthreads();

        __half* As = reinterpret_cast<__half*>(smem + (k & 1) * STAGE_BYTES);
        __half* Bs = As + BM * ASTR;
#pragma unroll
        for (int kk = 0; kk < BK; kk += 16) {
            wmma::fragment<wmma::matrix_a, 16, 16, 16, __half, wmma::row_major> af[4];
            wmma::fragment<wmma::matrix_b, 16, 16, 16, __half, wmma::col_major> bf[2];
#pragma unroll
            for (int i = 0; i < 4; i++)
                wmma::load_matrix_sync(af[i], As + (wm * 64 + i * 16) * ASTR + kk, ASTR);
#pragma unroll
            for (int j = 0; j < 2; j++)
                wmma::load_matrix_sync(bf[j], Bs + (wn * 32 + j * 16) * ASTR + kk, ASTR);
#pragma unroll
            for (int i = 0; i < 4; i++)
#pragma unroll
                for (int j = 0; j < 2; j++)
                    wmma::mma_sync(acc[i][j], af[i], bf[j], acc[i][j]);
        }
        __syncthreads();
    }
}

__device__ __forceinline__ void store_acc(float* Cs, AccFrag acc[4][2]) {
    int warp = threadIdx.x >> 5;
    int wm = warp & 1, wn = warp >> 1;
#pragma unroll
    for (int i = 0; i < 4; i++)
#pragma unroll
        for (int j = 0; j < 2; j++)
            wmma::store_matrix_sync(Cs + (wm * 64 + i * 16) * CSTR + wn * 32 + j * 16,
                                    acc[i][j], CSTR, wmma::mem_row_major);
}

// ---------------------------------------------------------------------------
// Projection GEMM + bias + RoPE; fp32 q/k to d_out, fp16 copies for scores
// ---------------------------------------------------------------------------
__global__ void __launch_bounds__(NTHREADS, 2) proj_cp_kernel(
    const float* __restrict__ bq, const float* __restrict__ bk,
    const float* __restrict__ embed, const int* __restrict__ posids,
    float* __restrict__ qout, float* __restrict__ kout)
{
    extern __shared__ __align__(128) char smem[];
    int z = blockIdx.z;
    const __half* W   = z ? g_wk : g_wq;
    const float* bias = z ? bk : bq;
    float* outp       = z ? kout : qout;
    __half* routp     = z ? g_kr : g_qr;
    const int m0 = blockIdx.x * BM;
    const int n0 = blockIdx.y * BN;

    AccFrag acc[4][2];
#pragma unroll
    for (int i = 0; i < 4; i++)
#pragma unroll
        for (int j = 0; j < 2; j++)
            wmma::fill_fragment(acc[i][j], 0.f);

    gemm_pipe<Ee / BK>(reinterpret_cast<const char*>(g_xnorm + (size_t)m0 * Ee),
                       reinterpret_cast<const char*>(W + (size_t)n0 * Ee),
                       (size_t)Ee * 2, smem, acc);

    float* Cs = reinterpret_cast<float*>(smem);
    store_acc(Cs, acc);
    __syncthreads();

    int tid = threadIdx.x;
#pragma unroll 4
    for (int i = 0; i < 32; i++) {
        int it = tid + i * NTHREADS;     // 0..8191 over 128x64 pairs
        int r = it >> 6;                 // 0..127
        int pc = it & 63;
        int c = pc << 1;
        int m = m0 + r, f = n0 + c;
        float v0 = Cs[r * CSTR + c] + bias[f];
        float v1 = Cs[r * CSTR + c + 1] + bias[f + 1];
        int d = f & 255;
        if (d < Rr) {
            int pos = posids[m];
            int i2 = d >> 1;
            float sn = embed[pos * Rr + i2];
            float co = embed[pos * Rr + 32 + i2];
            float o0 = v0 * co - v1 * sn;
            float o1 = v1 * co + v0 * sn;
            v0 = o0; v1 = o1;
        }
        int b_ = m >> 11, s_ = m & 2047, h_ = f >> 8;
        size_t off = ((size_t)(b_ * Hh + h_) * Ss + s_) * Dd + d;
        *reinterpret_cast<float2*>(outp + off) = make_float2(v0, v1);
        *reinterpret_cast<__half2*>(routp + off) = __floats2half2_rn(v0, v1);
    }
}

// ---------------------------------------------------------------------------
// Scores GEMM: scores = Qh.Kh^T / 16, causal tile skip
// ---------------------------------------------------------------------------
__global__ void __launch_bounds__(NTHREADS, 2) scores_cp_kernel(float* __restrict__ attn)
{
    int kt = blockIdx.x, qt = blockIdx.y, bh = blockIdx.z;
    if (kt > qt) return;

    extern __shared__ __align__(128) char smem[];
    int m0 = qt * BM, n0 = kt * BN;
    const __half* Q = g_qr + (size_t)bh * Ss * Dd;
    const __half* Kv = g_kr + (size_t)bh * Ss * Dd;

    AccFrag acc[4][2];
#pragma unroll
    for (int i = 0; i < 4; i++)
#pragma unroll
        for (int j = 0; j < 2; j++)
            wmma::fill_fragment(acc[i][j], 0.f);

    gemm_pipe<Dd / BK>(reinterpret_cast<const char*>(Q + (size_t)m0 * Dd),
                       reinterpret_cast<const char*>(Kv + (size_t)n0 * Dd),
                       (size_t)Dd * 2, smem, acc);

    float* Cs = reinterpret_cast<float*>(smem);
    store_acc(Cs, acc);
    __syncthreads();

    float* out_base = attn + (size_t)bh * Ss * Ss;
#pragma unroll
    for (int i = 0; i < 16; i++) {
        int it = threadIdx.x + i * NTHREADS;   // 0..4095 float4s over 128x128
        int r = it >> 5;
        int c4 = (it & 31) << 2;
        float4 v = *reinterpret_cast<const float4*>(Cs + r * CSTR + c4);
        v.x *= 0.0625f; v.y *= 0.0625f; v.z *= 0.0625f; v.w *= 0.0625f;
        *reinterpret_cast<float4*>(out_base + (size_t)(m0 + r) * Ss + n0 + c4) = v;
    }
}

// ---------------------------------------------------------------------------
// In-place masked softmax
// ---------------------------------------------------------------------------
__global__ void __launch_bounds__(256) softmax_kernel(float* __restrict__ attn) {
    int row = blockIdx.x;
    int q = row & 2047;
    int nv = q + 1;
    float* rowp = attn + (size_t)row * Ss;
    int tid = threadIdx.x;

    float vals[8];
    float mx = -INFINITY;
#pragma unroll
    for (int j = 0; j < 8; j++) {
        int k = tid + j * 256;
        float v = (k < nv) ? rowp[k] : -INFINITY;
        vals[j] = v;
        mx = fmaxf(mx, v);
    }
    __shared__ float sh[8];
#pragma unroll
    for (int o = 16; o; o >>= 1) mx = fmaxf(mx, __shfl_xor_sync(~0u, mx, o));
    if ((tid & 31) == 0) sh[tid >> 5] = mx;
    __syncthreads();
    if (tid < 32) {
        float t = (tid < 8) ? sh[tid] : -INFINITY;
#pragma unroll
        for (int o = 4; o; o >>= 1) t = fmaxf(t, __shfl_xor_sync(~0u, t, o));
        if (tid == 0) sh[0] = t;
    }
    __syncthreads();
    float M = sh[0];
    __syncthreads();

    float sum = 0.f;
#pragma unroll
    for (int j = 0; j < 8; j++) {
        int k = tid + j * 256;
        float e = (k < nv) ? expf(vals[j] - M) : 0.f;
        vals[j] = e;
        sum += e;
    }
#pragma unroll
    for (int o = 16; o; o >>= 1) sum += __shfl_xor_sync(~0u, sum, o);
    if ((tid & 31) == 0) sh[tid >> 5] = sum;
    __syncthreads();
    if (tid < 32) {
        float t = (tid < 8) ? sh[tid] : 0.f;
#pragma unroll
        for (int o = 4; o; o >>= 1) t += __shfl_xor_sync(~0u, t, o);
        if (tid == 0) sh[0] = t;
    }
    __syncthreads();
    float inv = 1.0f / sh[0];
#pragma unroll
    for (int j = 0; j < 8; j++) {
        int k = tid + j * 256;
        rowp[k] = vals[j] * inv;
    }
}

// ---------------------------------------------------------------------------
extern "C" void kernel_launch(void* const* d_in, const int* in_sizes, int n_in,
                              void* d_out, int out_size) {
    const float* x     = (const float*)d_in[0];
    const float* q_w   = (const float*)d_in[1];
    const float* q_b   = (const float*)d_in[2];
    const float* k_w   = (const float*)d_in[3];
    const float* k_b   = (const float*)d_in[4];
    const float* ln_w  = (const float*)d_in[5];
    const float* ln_b  = (const float*)d_in[6];
    const float* embed = (const float*)d_in[7];
    const int*   pos   = (const int*)d_in[8];

    float* out   = (float*)d_out;
    float* q_out = out;
    float* k_out = out + QK_ELEMS;
    float* attn  = out + 2 * QK_ELEMS;

    cudaFuncSetAttribute(proj_cp_kernel, cudaFuncAttributeMaxDynamicSharedMemorySize, (int)GEMM_SMEM);
    cudaFuncSetAttribute(scores_cp_kernel, cudaFuncAttributeMaxDynamicSharedMemorySize, (int)GEMM_SMEM);

    ln_kernel<<<Mtot, 256>>>(x, ln_w, ln_b);

    dim3 gw((unsigned)(((size_t)Ee * Ee) / 1024), 2);   // 16384 x 2
    wconv_kernel<<<gw, 256>>>(q_w, k_w);

    dim3 gp(Mtot / BM, Ee / BN, 2);          // (32, 32, 2), x over M
    proj_cp_kernel<<<gp, NTHREADS, GEMM_SMEM>>>(q_b, k_b, embed, pos, q_out, k_out);

    dim3 g2(Ss / BN, Ss / BM, Bb * Hh);      // (16, 16, 32)
    scores_cp_kernel<<<g2, NTHREADS, GEMM_SMEM>>>(attn);

    softmax_kernel<<<Bb * Hh * Ss, 256>>>(attn);
}